// round 13
// baseline (speedup 1.0000x reference)
#include <cuda_runtime.h>
#include <cuda_bf16.h>
#include <stdint.h>
#include <math.h>

// ---------------- problem constants ----------------
#define BQ      8
#define C_INN   112
#define HH      16
#define WWW     16
#define DD      128
#define N_BANK  200000
#define NB_PAD  200064          // 1563 * 128 (pad rows zeroed -> sim 0, never top-3)
#define N_TILES 1563
#define NS      18              // bank slices; 16*18 = 288 CTAs = 2 per SM
#define PER_SL  87              // ceil(1563/18)
#define QTOT    2048
#define QT      16
#define QTILE   128
#define LDSS    136             // smem row stride in bf16 (272B -> conflict-free ldmatrix)
#define TILE_SM (QTILE * LDSS)  // bf16 elements per smem tile (34816 B)

// ---------------- device scratch (no allocs allowed) ----------------
__device__ __nv_bfloat16 g_bank[(size_t)NB_PAD * DD];   // 51.2 MB normalized bf16 bank
__device__ __nv_bfloat16 g_q[QTOT * DD];                // normalized bf16 queries
__device__ float g_partial[QTOT * NS * 3];              // query-major: [q][slice][3]
__device__ int   g_done = 0;                            // CTA completion counter

// ---------------- helpers ----------------
__device__ __forceinline__ void ins3(float v, float& s0, float& s1, float& s2) {
    float m  = fminf(s0, v);
    s0 = fmaxf(s0, v);
    float m2 = fminf(s1, m);
    s1 = fmaxf(s1, m);
    s2 = fmaxf(s2, m2);
}

// ---------------- 1) patch embedding + L2 norm -> bf16 ----------------
__global__ void embed_kernel(const float* __restrict__ fm, const float* __restrict__ w) {
    __shared__ float xs[8][C_INN];
    __shared__ float es[8][DD];
    __shared__ float inv[8];
    const int t = threadIdx.x;          // 128 threads
    const int qbase = blockIdx.x * 8;

    for (int idx = t; idx < 8 * C_INN; idx += 128) {
        int qi = idx / C_INN, c = idx % C_INN;
        int q = qbase + qi;
        int b = q >> 8, p = q & 255;
        int y = p >> 4, x = p & 15;
        xs[qi][c] = fm[((b * C_INN + c) * HH + y) * WWW + x];
    }
    __syncthreads();

    const int d = t;
    float acc[8];
#pragma unroll
    for (int qi = 0; qi < 8; qi++) acc[qi] = 0.f;
    for (int c = 0; c < C_INN; c++) {
        float wv = w[d * C_INN + c];
#pragma unroll
        for (int qi = 0; qi < 8; qi++) acc[qi] += xs[qi][c] * wv;
    }
#pragma unroll
    for (int qi = 0; qi < 8; qi++) es[qi][d] = acc[qi];
    __syncthreads();

    if (t < 8) {
        float ss = 0.f;
        for (int dd2 = 0; dd2 < DD; dd2++) { float v = es[t][dd2]; ss += v * v; }
        inv[t] = 1.0f / fmaxf(sqrtf(ss), 1e-12f);
    }
    __syncthreads();
#pragma unroll
    for (int qi = 0; qi < 8; qi++)
        g_q[(qbase + qi) * DD + t] = __float2bfloat16(es[qi][t] * inv[qi]);
}

// ---------------- 2) bank L2 norm -> bf16, MLP=8 DRAM-bound version ----------------
// 512 threads = 16 warps; each warp handles 8 rows (8 independent LDG.128/lane,
// interleaved shfl chains, coalesced 8B store per lane per row).
__global__ void __launch_bounds__(512) bank_norm_kernel(const float* __restrict__ bank) {
    const int wid = threadIdx.x >> 5, lane = threadIdx.x & 31;
    const int row0 = blockIdx.x * 128 + wid * 8;

    float4 v[8];
    float ss[8];
#pragma unroll
    for (int r = 0; r < 8; r++) {
        const int row = row0 + r;
        if (row < N_BANK) {
            v[r] = ((const float4*)(bank + (size_t)row * DD))[lane];
        } else {
            v[r] = make_float4(0.f, 0.f, 0.f, 0.f);
        }
    }
#pragma unroll
    for (int r = 0; r < 8; r++)
        ss[r] = v[r].x * v[r].x + v[r].y * v[r].y + v[r].z * v[r].z + v[r].w * v[r].w;
#pragma unroll
    for (int m = 16; m > 0; m >>= 1) {
#pragma unroll
        for (int r = 0; r < 8; r++)
            ss[r] += __shfl_xor_sync(0xffffffffu, ss[r], m);
    }
#pragma unroll
    for (int r = 0; r < 8; r++) {
        float inv = 1.0f / fmaxf(sqrtf(ss[r]), 1e-12f);   // pad rows: 0 stays 0
        __nv_bfloat162 lo = __floats2bfloat162_rn(v[r].x * inv, v[r].y * inv);
        __nv_bfloat162 hi = __floats2bfloat162_rn(v[r].z * inv, v[r].w * inv);
        uint2 o;
        o.x = *(unsigned*)&lo;
        o.y = *(unsigned*)&hi;
        *(uint2*)(g_bank + (size_t)(row0 + r) * DD + lane * 4) = o;
    }
}

// ---------------- 3) fused GEMM + streaming top-3 + last-CTA finalize ----------------
// grid (NS, QT), 256 threads = 8 warps (4 M-strips x 2 N-halves), 2 CTAs/SM.
// R6 mainloop verbatim. After g_partial write, the LAST CTA (atomic counter)
// performs the whole merge + dist + per-batch top-8 (warp w = batch w).
__global__ void __launch_bounds__(256, 2) sim_topk_kernel(float* __restrict__ out) {
    extern __shared__ __align__(16) __nv_bfloat16 smem[];
    __nv_bfloat16* q_sm = smem;                 // [128][136]
    __nv_bfloat16* b_sm = smem + TILE_SM;       // 2 stages of [128][136]

    const int t = threadIdx.x;
    const int lane = t & 31, w = t >> 5;
    const int slice = blockIdx.x, qt = blockIdx.y;
    const int wm = (w >> 1) * 32;       // warp M base (queries)
    const int wn = (w & 1) * 64;        // warp N base (bank cols)
    const int tb = slice * PER_SL;
    const int nt = min(tb + PER_SL, N_TILES) - tb;

    // A (query) tile -> smem, once
    {
        const uint4* src = (const uint4*)(g_q + (size_t)qt * QTILE * DD);
#pragma unroll
        for (int it = 0; it < 8; it++) {
            int u = t + it * 256;
            int row = u >> 4, c16 = u & 15;
            *(uint4*)(q_sm + row * LDSS + c16 * 8) = src[u];
        }
    }

    const unsigned b_base = (unsigned)__cvta_generic_to_shared(b_sm);

    // issue one B tile into a stage via cp.async (8 x 16B per thread)
    auto issue_b = [&](int stage, int tile) {
        const char* src = (const char*)(g_bank + (size_t)tile * QTILE * DD);
        const unsigned dst0 = b_base + stage * (TILE_SM * 2);
#pragma unroll
        for (int it = 0; it < 8; it++) {
            int u = t + it * 256;
            int row = u >> 4, c16 = u & 15;
            unsigned dst = dst0 + row * (LDSS * 2) + c16 * 16;
            asm volatile("cp.async.cg.shared.global [%0], [%1], 16;\n"
                         :: "r"(dst), "l"(src + (size_t)u * 16));
        }
    };

    // prologue: tile 0 -> stage 0
    issue_b(0, tb);
    asm volatile("cp.async.commit_group;\n" ::: "memory");

    float run[4][3];
#pragma unroll
    for (int i = 0; i < 4; i++) { run[i][0] = -3.f; run[i][1] = -3.f; run[i][2] = -3.f; }

    // per-lane ldmatrix address components (validated in R3/R6)
    const int a_row = (lane & 15);
    const int a_coff = (lane >= 16) ? 8 : 0;
    const int b_row = (lane & 7) + ((lane >= 16) ? 8 : 0);
    const int b_coff = (lane & 8) ? 8 : 0;

    for (int i = 0; i < nt; i++) {
        if (i + 1 < nt) issue_b((i + 1) & 1, tb + i + 1);
        asm volatile("cp.async.commit_group;\n" ::: "memory");
        asm volatile("cp.async.wait_group %0;\n" :: "n"(1) : "memory");
        __syncthreads();   // tile i visible to all; previous stage reads done

        const __nv_bfloat16* bs = b_sm + (i & 1) * TILE_SM;

        float acc[2][8][4];
#pragma unroll
        for (int a = 0; a < 2; a++)
#pragma unroll
            for (int j = 0; j < 8; j++)
#pragma unroll
                for (int r = 0; r < 4; r++) acc[a][j][r] = 0.f;

#pragma unroll
        for (int ks = 0; ks < 8; ks++) {
            const int kb = ks * 16;
            unsigned a[2][4];
#pragma unroll
            for (int ai = 0; ai < 2; ai++) {
                unsigned addr = (unsigned)__cvta_generic_to_shared(
                    q_sm + (wm + ai * 16 + a_row) * LDSS + kb + a_coff);
                asm volatile(
                    "ldmatrix.sync.aligned.m8n8.x4.shared.b16 {%0,%1,%2,%3}, [%4];\n"
                    : "=r"(a[ai][0]), "=r"(a[ai][1]), "=r"(a[ai][2]), "=r"(a[ai][3])
                    : "r"(addr));
            }
#pragma unroll
            for (int jp = 0; jp < 4; jp++) {
                unsigned b0, b1, b2, b3;
                unsigned addr = (unsigned)__cvta_generic_to_shared(
                    bs + (wn + jp * 16 + b_row) * LDSS + kb + b_coff);
                asm volatile(
                    "ldmatrix.sync.aligned.m8n8.x4.shared.b16 {%0,%1,%2,%3}, [%4];\n"
                    : "=r"(b0), "=r"(b1), "=r"(b2), "=r"(b3)
                    : "r"(addr));
#pragma unroll
                for (int ai = 0; ai < 2; ai++) {
                    asm volatile(
                        "mma.sync.aligned.m16n8k16.row.col.f32.bf16.bf16.f32 "
                        "{%0,%1,%2,%3},{%4,%5,%6,%7},{%8,%9},{%0,%1,%2,%3};\n"
                        : "+f"(acc[ai][2 * jp][0]), "+f"(acc[ai][2 * jp][1]),
                          "+f"(acc[ai][2 * jp][2]), "+f"(acc[ai][2 * jp][3])
                        : "r"(a[ai][0]), "r"(a[ai][1]), "r"(a[ai][2]), "r"(a[ai][3]),
                          "r"(b0), "r"(b1));
                    asm volatile(
                        "mma.sync.aligned.m16n8k16.row.col.f32.bf16.bf16.f32 "
                        "{%0,%1,%2,%3},{%4,%5,%6,%7},{%8,%9},{%0,%1,%2,%3};\n"
                        : "+f"(acc[ai][2 * jp + 1][0]), "+f"(acc[ai][2 * jp + 1][1]),
                          "+f"(acc[ai][2 * jp + 1][2]), "+f"(acc[ai][2 * jp + 1][3])
                        : "r"(a[ai][0]), "r"(a[ai][1]), "r"(a[ai][2]), "r"(a[ai][3]),
                          "r"(b2), "r"(b3));
                }
            }
        }

        // screened per-lane top-3: max-tree over the 16 values of each
        // (M-half, row-half) group; full insert only if it can change top-3.
#pragma unroll
        for (int i2 = 0; i2 < 2; i2++) {
#pragma unroll
            for (int hi = 0; hi < 2; hi++) {
                float m[8];
#pragma unroll
                for (int j = 0; j < 8; j++)
                    m[j] = fmaxf(acc[i2][j][2 * hi], acc[i2][j][2 * hi + 1]);
#pragma unroll
                for (int s = 4; s > 0; s >>= 1)
#pragma unroll
                    for (int j = 0; j < s; j++) m[j] = fmaxf(m[j], m[j + s]);
                const int idx = i2 * 2 + hi;
                if (m[0] > run[idx][2]) {
#pragma unroll
                    for (int j = 0; j < 8; j++) {
                        ins3(acc[i2][j][2 * hi],     run[idx][0], run[idx][1], run[idx][2]);
                        ins3(acc[i2][j][2 * hi + 1], run[idx][0], run[idx][1], run[idx][2]);
                    }
                }
            }
        }
        __syncthreads();   // all reads of stage (i&1) done before next overwrite
    }

    // ---- final merge: lanes sharing a row (xor 1,2), then the two N-halves ----
    float* fsm = (float*)smem;   // reuse smem as [128 rows][2 halves][3] staging
#pragma unroll
    for (int idx = 0; idx < 4; idx++) {
        float s0 = run[idx][0], s1 = run[idx][1], s2 = run[idx][2];
#pragma unroll
        for (int m = 1; m <= 2; m <<= 1) {
            float o0 = __shfl_xor_sync(0xffffffffu, s0, m);
            float o1 = __shfl_xor_sync(0xffffffffu, s1, m);
            float o2 = __shfl_xor_sync(0xffffffffu, s2, m);
            ins3(o0, s0, s1, s2); ins3(o1, s0, s1, s2); ins3(o2, s0, s1, s2);
        }
        if ((lane & 3) == 0) {
            int row = wm + (idx >> 1) * 16 + (lane >> 2) + ((idx & 1) << 3);
            fsm[(row * 2 + (w & 1)) * 3 + 0] = s0;
            fsm[(row * 2 + (w & 1)) * 3 + 1] = s1;
            fsm[(row * 2 + (w & 1)) * 3 + 2] = s2;
        }
    }
    __syncthreads();
    if (t < QTILE) {
        float s0 = fsm[(t * 2) * 3 + 0], s1 = fsm[(t * 2) * 3 + 1], s2 = fsm[(t * 2) * 3 + 2];
        ins3(fsm[(t * 2 + 1) * 3 + 0], s0, s1, s2);
        ins3(fsm[(t * 2 + 1) * 3 + 1], s0, s1, s2);
        ins3(fsm[(t * 2 + 1) * 3 + 2], s0, s1, s2);
        // query-major layout: [q][slice][3]
        float* dst = g_partial + (((size_t)(qt * QTILE + t)) * NS + slice) * 3;
        dst[0] = s0; dst[1] = s1; dst[2] = s2;
    }

    // ---- last-CTA finalize (warp w = batch w; 8 queries per thread) ----
    __threadfence();
    __syncthreads();
    __shared__ int s_last;
    if (t == 0) {
        int c = atomicAdd(&g_done, 1);
        s_last = (c == NS * QT - 1) ? 1 : 0;
    }
    __syncthreads();
    if (!s_last) return;
    __threadfence();   // acquire: all CTAs' g_partial writes visible

    float pd[8];
#pragma unroll
    for (int k = 0; k < 8; k++) {
        const int q = t * 8 + k;                       // warp w owns queries of batch w
        const float* p = g_partial + (size_t)q * NS * 3;
        float s0 = -3.f, s1 = -3.f, s2 = -3.f;
#pragma unroll
        for (int s = 0; s < NS; s++) {
            ins3(p[s * 3 + 0], s0, s1, s2);
            ins3(p[s * 3 + 1], s0, s1, s2);
            ins3(p[s * 3 + 2], s0, s1, s2);
        }
        float d0 = sqrtf(fmaxf(2.f - 2.f * s0, 0.f));
        float d1 = sqrtf(fmaxf(2.f - 2.f * s1, 0.f));
        float d2 = sqrtf(fmaxf(2.f - 2.f * s2, 0.f));
        pd[k] = (d0 + d1 + d2) * (1.f / 3.f);
    }

    // per-warp (= per-batch) top-8 knockout over 256 values
    float sum = 0.f;
#pragma unroll
    for (int it = 0; it < 8; it++) {
        float lm = pd[0];
#pragma unroll
        for (int k = 1; k < 8; k++) lm = fmaxf(lm, pd[k]);
        float mx = lm;
#pragma unroll
        for (int m = 16; m > 0; m >>= 1)
            mx = fmaxf(mx, __shfl_xor_sync(0xffffffffu, mx, m));
        sum += mx;
        unsigned bal = __ballot_sync(0xffffffffu, lm == mx);
        if (lane == (int)(__ffs(bal) - 1)) {
            bool done = false;
#pragma unroll
            for (int k = 0; k < 8; k++) {
                if (!done && pd[k] == mx) { pd[k] = -1e30f; done = true; }
            }
        }
    }
    if (lane == 0) out[w] = sum * 0.125f;   // k = ceil(256*0.03) = 8

    __syncthreads();
    if (t == 0) g_done = 0;   // reset for next graph replay (determinism)
}

// ---------------- launch ----------------
extern "C" void kernel_launch(void* const* d_in, const int* in_sizes, int n_in,
                              void* d_out, int out_size) {
    const float* fm   = (const float*)d_in[0];  // [8,112,16,16]
    const float* w    = (const float*)d_in[1];  // [128,112]
    const float* bank = (const float*)d_in[2];  // [200000,128]
    float* out = (float*)d_out;                 // [8]

    embed_kernel<<<QTOT / 8, 128>>>(fm, w);
    bank_norm_kernel<<<NB_PAD / 128, 512>>>(bank);

    const int smem_bytes = 3 * TILE_SM * (int)sizeof(__nv_bfloat16);  // 104448
    cudaFuncSetAttribute(sim_topk_kernel,
                         cudaFuncAttributeMaxDynamicSharedMemorySize, smem_bytes);
    dim3 grid(NS, QT);
    sim_topk_kernel<<<grid, 256, smem_bytes>>>(out);
}

// round 14
// speedup vs baseline: 1.1689x; 1.1689x over previous
#include <cuda_runtime.h>
#include <cuda_bf16.h>
#include <stdint.h>
#include <math.h>

// ---------------- problem constants ----------------
#define BQ      8
#define C_INN   112
#define HH      16
#define WWW     16
#define DD      128
#define N_BANK  200000
#define NB_PAD  200064          // 1563 * 128 (pad rows zeroed -> sim 0, never top-3)
#define N_TILES 1563
#define NS      18              // bank slices; 16*18 = 288 CTAs = 2 per SM
#define PER_SL  87              // ceil(1563/18)
#define QTOT    2048
#define QT      16
#define QTILE   128
#define LDSS    136             // smem row stride in bf16 (272B -> conflict-free ldmatrix)
#define TILE_SM (QTILE * LDSS)  // bf16 elements per smem tile (34816 B)
#define WSTR    113             // padded smem stride for the weight matrix

// ---------------- device scratch (no allocs allowed) ----------------
__device__ __nv_bfloat16 g_bank[(size_t)NB_PAD * DD];   // 51.2 MB normalized bf16 bank
__device__ __nv_bfloat16 g_q[QTOT * DD];                // normalized bf16 queries
__device__ float g_partial[QT * NS * QTILE * 3];        // per-(qtile,slice,row) top-3 sims

// ---------------- helpers ----------------
__device__ __forceinline__ void ins3(float v, float& s0, float& s1, float& s2) {
    float m  = fminf(s0, v);
    s0 = fmaxf(s0, v);
    float m2 = fminf(s1, m);
    s1 = fmaxf(s1, m);
    s2 = fmaxf(s2, m2);
}

// ---------------- 1) patch embedding + L2 norm -> bf16 ----------------
// w staged in dynamic smem (coalesced load, stride-113 -> conflict-free LDS).
__global__ void embed_kernel(const float* __restrict__ fm, const float* __restrict__ w) {
    extern __shared__ float dyn[];
    float* ws  = dyn;                    // [128][113] padded weights
    float* xs  = ws + DD * WSTR;         // [8][112]
    float* es  = xs + 8 * C_INN;         // [8][128]
    float* inv = es + 8 * DD;            // [8]
    const int t = threadIdx.x;           // 128 threads
    const int qbase = blockIdx.x * 8;

    // coalesced weight load into padded smem
    for (int idx = t; idx < DD * C_INN; idx += 128) {
        int d = idx / C_INN, c = idx % C_INN;
        ws[d * WSTR + c] = w[idx];
    }
    for (int idx = t; idx < 8 * C_INN; idx += 128) {
        int qi = idx / C_INN, c = idx % C_INN;
        int q = qbase + qi;
        int b = q >> 8, p = q & 255;
        int y = p >> 4, x = p & 15;
        xs[qi * C_INN + c] = fm[((b * C_INN + c) * HH + y) * WWW + x];
    }
    __syncthreads();

    const int d = t;
    float acc[8];
#pragma unroll
    for (int qi = 0; qi < 8; qi++) acc[qi] = 0.f;
    for (int c = 0; c < C_INN; c++) {
        float wv = ws[d * WSTR + c];     // conflict-free: 17*d mod 32 full cycle
#pragma unroll
        for (int qi = 0; qi < 8; qi++) acc[qi] += xs[qi * C_INN + c] * wv;
    }
#pragma unroll
    for (int qi = 0; qi < 8; qi++) es[qi * DD + d] = acc[qi];
    __syncthreads();

    if (t < 8) {
        float ss = 0.f;
        for (int dd2 = 0; dd2 < DD; dd2++) { float v = es[t * DD + dd2]; ss += v * v; }
        inv[t] = 1.0f / fmaxf(sqrtf(ss), 1e-12f);
    }
    __syncthreads();
#pragma unroll
    for (int qi = 0; qi < 8; qi++)
        g_q[(qbase + qi) * DD + t] = __float2bfloat16(es[qi * DD + t] * inv[qi]);
}

// ---------------- 2) bank L2 norm -> bf16 (zero padding rows) ----------------
__global__ void bank_norm_kernel(const float* __restrict__ bank) {
    const int wid = threadIdx.x >> 5, lane = threadIdx.x & 31;
    const long long row = (long long)blockIdx.x * 8 + wid;
    if (row >= NB_PAD) return;
    __nv_bfloat162* dst = (__nv_bfloat162*)(g_bank + (size_t)row * DD);
    if (row < N_BANK) {
        float4 v = ((const float4*)(bank + (size_t)row * DD))[lane];
        float ss = v.x * v.x + v.y * v.y + v.z * v.z + v.w * v.w;
#pragma unroll
        for (int m = 16; m > 0; m >>= 1) ss += __shfl_xor_sync(0xffffffffu, ss, m);
        float inv = 1.0f / fmaxf(sqrtf(ss), 1e-12f);
        dst[lane * 2]     = __floats2bfloat162_rn(v.x * inv, v.y * inv);
        dst[lane * 2 + 1] = __floats2bfloat162_rn(v.z * inv, v.w * inv);
    } else {
        dst[lane * 2]     = __floats2bfloat162_rn(0.f, 0.f);
        dst[lane * 2 + 1] = __floats2bfloat162_rn(0.f, 0.f);
    }
}

// ---------------- 3) fused GEMM + streaming top-3 (R6 core, unchanged) ----------------
// grid (NS, QT), 256 threads = 8 warps (4 M-strips x 2 N-halves), 2 CTAs/SM.
// 2-stage cp.async pipeline on B tiles; per-lane running top-3 per fragment
// row-group, screened by a max-tree; cross-lane merge once at the end.
__global__ void __launch_bounds__(256, 2) sim_topk_kernel() {
    extern __shared__ __align__(16) __nv_bfloat16 smem[];
    __nv_bfloat16* q_sm = smem;                 // [128][136]
    __nv_bfloat16* b_sm = smem + TILE_SM;       // 2 stages of [128][136]

    const int t = threadIdx.x;
    const int lane = t & 31, w = t >> 5;
    const int slice = blockIdx.x, qt = blockIdx.y;
    const int wm = (w >> 1) * 32;       // warp M base (queries)
    const int wn = (w & 1) * 64;        // warp N base (bank cols)
    const int tb = slice * PER_SL;
    const int nt = min(tb + PER_SL, N_TILES) - tb;

    // A (query) tile -> smem, once
    {
        const uint4* src = (const uint4*)(g_q + (size_t)qt * QTILE * DD);
#pragma unroll
        for (int it = 0; it < 8; it++) {
            int u = t + it * 256;
            int row = u >> 4, c16 = u & 15;
            *(uint4*)(q_sm + row * LDSS + c16 * 8) = src[u];
        }
    }

    const unsigned b_base = (unsigned)__cvta_generic_to_shared(b_sm);

    // issue one B tile into a stage via cp.async (8 x 16B per thread)
    auto issue_b = [&](int stage, int tile) {
        const char* src = (const char*)(g_bank + (size_t)tile * QTILE * DD);
        const unsigned dst0 = b_base + stage * (TILE_SM * 2);
#pragma unroll
        for (int it = 0; it < 8; it++) {
            int u = t + it * 256;
            int row = u >> 4, c16 = u & 15;
            unsigned dst = dst0 + row * (LDSS * 2) + c16 * 16;
            asm volatile("cp.async.cg.shared.global [%0], [%1], 16;\n"
                         :: "r"(dst), "l"(src + (size_t)u * 16));
        }
    };

    // prologue: tile 0 -> stage 0
    issue_b(0, tb);
    asm volatile("cp.async.commit_group;\n" ::: "memory");

    float run[4][3];
#pragma unroll
    for (int i = 0; i < 4; i++) { run[i][0] = -3.f; run[i][1] = -3.f; run[i][2] = -3.f; }

    // per-lane ldmatrix address components (validated in R3/R6)
    const int a_row = (lane & 15);
    const int a_coff = (lane >= 16) ? 8 : 0;
    const int b_row = (lane & 7) + ((lane >= 16) ? 8 : 0);
    const int b_coff = (lane & 8) ? 8 : 0;

    for (int i = 0; i < nt; i++) {
        if (i + 1 < nt) issue_b((i + 1) & 1, tb + i + 1);
        asm volatile("cp.async.commit_group;\n" ::: "memory");
        asm volatile("cp.async.wait_group %0;\n" :: "n"(1) : "memory");
        __syncthreads();   // tile i visible to all; previous stage reads done

        const __nv_bfloat16* bs = b_sm + (i & 1) * TILE_SM;

        float acc[2][8][4];
#pragma unroll
        for (int a = 0; a < 2; a++)
#pragma unroll
            for (int j = 0; j < 8; j++)
#pragma unroll
                for (int r = 0; r < 4; r++) acc[a][j][r] = 0.f;

#pragma unroll
        for (int ks = 0; ks < 8; ks++) {
            const int kb = ks * 16;
            unsigned a[2][4];
#pragma unroll
            for (int ai = 0; ai < 2; ai++) {
                unsigned addr = (unsigned)__cvta_generic_to_shared(
                    q_sm + (wm + ai * 16 + a_row) * LDSS + kb + a_coff);
                asm volatile(
                    "ldmatrix.sync.aligned.m8n8.x4.shared.b16 {%0,%1,%2,%3}, [%4];\n"
                    : "=r"(a[ai][0]), "=r"(a[ai][1]), "=r"(a[ai][2]), "=r"(a[ai][3])
                    : "r"(addr));
            }
#pragma unroll
            for (int jp = 0; jp < 4; jp++) {
                unsigned b0, b1, b2, b3;
                unsigned addr = (unsigned)__cvta_generic_to_shared(
                    bs + (wn + jp * 16 + b_row) * LDSS + kb + b_coff);
                asm volatile(
                    "ldmatrix.sync.aligned.m8n8.x4.shared.b16 {%0,%1,%2,%3}, [%4];\n"
                    : "=r"(b0), "=r"(b1), "=r"(b2), "=r"(b3)
                    : "r"(addr));
#pragma unroll
                for (int ai = 0; ai < 2; ai++) {
                    asm volatile(
                        "mma.sync.aligned.m16n8k16.row.col.f32.bf16.bf16.f32 "
                        "{%0,%1,%2,%3},{%4,%5,%6,%7},{%8,%9},{%0,%1,%2,%3};\n"
                        : "+f"(acc[ai][2 * jp][0]), "+f"(acc[ai][2 * jp][1]),
                          "+f"(acc[ai][2 * jp][2]), "+f"(acc[ai][2 * jp][3])
                        : "r"(a[ai][0]), "r"(a[ai][1]), "r"(a[ai][2]), "r"(a[ai][3]),
                          "r"(b0), "r"(b1));
                    asm volatile(
                        "mma.sync.aligned.m16n8k16.row.col.f32.bf16.bf16.f32 "
                        "{%0,%1,%2,%3},{%4,%5,%6,%7},{%8,%9},{%0,%1,%2,%3};\n"
                        : "+f"(acc[ai][2 * jp + 1][0]), "+f"(acc[ai][2 * jp + 1][1]),
                          "+f"(acc[ai][2 * jp + 1][2]), "+f"(acc[ai][2 * jp + 1][3])
                        : "r"(a[ai][0]), "r"(a[ai][1]), "r"(a[ai][2]), "r"(a[ai][3]),
                          "r"(b2), "r"(b3));
                }
            }
        }

        // screened per-lane top-3: max-tree over the 16 values of each
        // (M-half, row-half) group; full insert only if it can change top-3.
#pragma unroll
        for (int i2 = 0; i2 < 2; i2++) {
#pragma unroll
            for (int hi = 0; hi < 2; hi++) {
                float m[8];
#pragma unroll
                for (int j = 0; j < 8; j++)
                    m[j] = fmaxf(acc[i2][j][2 * hi], acc[i2][j][2 * hi + 1]);
#pragma unroll
                for (int s = 4; s > 0; s >>= 1)
#pragma unroll
                    for (int j = 0; j < s; j++) m[j] = fmaxf(m[j], m[j + s]);
                const int idx = i2 * 2 + hi;
                if (m[0] > run[idx][2]) {
#pragma unroll
                    for (int j = 0; j < 8; j++) {
                        ins3(acc[i2][j][2 * hi],     run[idx][0], run[idx][1], run[idx][2]);
                        ins3(acc[i2][j][2 * hi + 1], run[idx][0], run[idx][1], run[idx][2]);
                    }
                }
            }
        }
        __syncthreads();   // all reads of stage (i&1) done before next overwrite
    }

    // ---- final merge: lanes sharing a row (xor 1,2), then the two N-halves ----
    float* fsm = (float*)smem;   // reuse smem as [128 rows][2 halves][3] staging
#pragma unroll
    for (int idx = 0; idx < 4; idx++) {
        float s0 = run[idx][0], s1 = run[idx][1], s2 = run[idx][2];
#pragma unroll
        for (int m = 1; m <= 2; m <<= 1) {
            float o0 = __shfl_xor_sync(0xffffffffu, s0, m);
            float o1 = __shfl_xor_sync(0xffffffffu, s1, m);
            float o2 = __shfl_xor_sync(0xffffffffu, s2, m);
            ins3(o0, s0, s1, s2); ins3(o1, s0, s1, s2); ins3(o2, s0, s1, s2);
        }
        if ((lane & 3) == 0) {
            int row = wm + (idx >> 1) * 16 + (lane >> 2) + ((idx & 1) << 3);
            fsm[(row * 2 + (w & 1)) * 3 + 0] = s0;
            fsm[(row * 2 + (w & 1)) * 3 + 1] = s1;
            fsm[(row * 2 + (w & 1)) * 3 + 2] = s2;
        }
    }
    __syncthreads();
    if (t < QTILE) {
        float s0 = fsm[(t * 2) * 3 + 0], s1 = fsm[(t * 2) * 3 + 1], s2 = fsm[(t * 2) * 3 + 2];
        ins3(fsm[(t * 2 + 1) * 3 + 0], s0, s1, s2);
        ins3(fsm[(t * 2 + 1) * 3 + 1], s0, s1, s2);
        ins3(fsm[(t * 2 + 1) * 3 + 2], s0, s1, s2);
        float* dst = g_partial + (((size_t)qt * NS + slice) * QTILE + t) * 3;
        dst[0] = s0; dst[1] = s1; dst[2] = s2;
    }
}

// ---------------- 4) merge slices, per-query dist, per-batch top-8 mean ----------------
__global__ void finalize_kernel(float* __restrict__ out) {
    __shared__ float cand[64];
    const int b = blockIdx.x, t = threadIdx.x;     // 256 threads = 256 patches of batch b
    const int lane = t & 31, wid = t >> 5;
    const int q = b * 256 + t;
    const int qt = q >> 7, row = q & 127;
    float s0 = -3.f, s1 = -3.f, s2 = -3.f;
    for (int s = 0; s < NS; s++) {
        const float* p = g_partial + (((size_t)qt * NS + s) * QTILE + row) * 3;
        ins3(p[0], s0, s1, s2); ins3(p[1], s0, s1, s2); ins3(p[2], s0, s1, s2);
    }
    float d0 = sqrtf(fmaxf(2.f - 2.f * s0, 0.f));
    float d1 = sqrtf(fmaxf(2.f - 2.f * s1, 0.f));
    float d2 = sqrtf(fmaxf(2.f - 2.f * s2, 0.f));
    float x = (d0 + d1 + d2) * (1.f / 3.f);

    // warp-local top-8 by knockout max-reduction
    for (int it = 0; it < 8; it++) {
        float mx = x;
        for (int m = 16; m > 0; m >>= 1)
            mx = fmaxf(mx, __shfl_xor_sync(0xffffffffu, mx, m));
        unsigned bal = __ballot_sync(0xffffffffu, x == mx);
        if (lane == 0) cand[wid * 8 + it] = mx;
        if (lane == (int)(__ffs(bal) - 1)) x = -1e30f;
    }
    __syncthreads();
    if (t == 0) {
        float top[8];
        for (int i = 0; i < 8; i++) top[i] = -1e30f;
        for (int i = 0; i < 64; i++) {
            float v = cand[i];
            if (v > top[7]) {
                int j = 7;
                while (j > 0 && top[j - 1] < v) { top[j] = top[j - 1]; j--; }
                top[j] = v;
            }
        }
        float sum = 0.f;
        for (int i = 0; i < 8; i++) sum += top[i];
        out[b] = sum * 0.125f;   // k = ceil(256*0.03) = 8
    }
}

// ---------------- launch ----------------
extern "C" void kernel_launch(void* const* d_in, const int* in_sizes, int n_in,
                              void* d_out, int out_size) {
    const float* fm   = (const float*)d_in[0];  // [8,112,16,16]
    const float* w    = (const float*)d_in[1];  // [128,112]
    const float* bank = (const float*)d_in[2];  // [200000,128]
    float* out = (float*)d_out;                 // [8]

    const int embed_smem = (DD * WSTR + 8 * C_INN + 8 * DD + 8) * (int)sizeof(float);
    cudaFuncSetAttribute(embed_kernel,
                         cudaFuncAttributeMaxDynamicSharedMemorySize, embed_smem);
    embed_kernel<<<QTOT / 8, 128, embed_smem>>>(fm, w);
    bank_norm_kernel<<<NB_PAD / 8, 256>>>(bank);

    const int smem_bytes = 3 * TILE_SM * (int)sizeof(__nv_bfloat16);  // 104448
    cudaFuncSetAttribute(sim_topk_kernel,
                         cudaFuncAttributeMaxDynamicSharedMemorySize, smem_bytes);
    dim3 grid(NS, QT);
    sim_topk_kernel<<<grid, 256, smem_bytes>>>();

    finalize_kernel<<<BQ, 256>>>(out);
}

// round 15
// speedup vs baseline: 1.1814x; 1.0107x over previous
#include <cuda_runtime.h>
#include <cuda_bf16.h>
#include <stdint.h>
#include <math.h>

// ---------------- problem constants ----------------
#define BQ      8
#define C_INN   112
#define HH      16
#define WWW     16
#define DD      128
#define N_BANK  200000
#define NB_PAD  200064          // 1563 * 128 (pad rows zeroed -> sim 0, never top-3)
#define N_TILES 1563
#define NS      18              // bank slices; 16*18 = 288 CTAs = 2 per SM
#define PER_SL  87              // ceil(1563/18)
#define QTOT    2048
#define QT      16
#define QTILE   128
#define LDSS    136             // smem row stride in bf16 (272B -> conflict-free ldmatrix)
#define TILE_SM (QTILE * LDSS)  // bf16 elements per smem tile (34816 B)
#define WSTR    113             // padded smem stride for the weight matrix

// ---------------- device scratch (no allocs allowed) ----------------
__device__ __nv_bfloat16 g_bank[(size_t)NB_PAD * DD];   // 51.2 MB normalized bf16 bank
__device__ __nv_bfloat16 g_q[QTOT * DD];                // normalized bf16 queries
__device__ float g_partial[QT * NS * QTILE * 3];        // per-(qtile,slice,row) top-3 sims

// ---------------- helpers ----------------
__device__ __forceinline__ void ins3(float v, float& s0, float& s1, float& s2) {
    float m  = fminf(s0, v);
    s0 = fmaxf(s0, v);
    float m2 = fminf(s1, m);
    s1 = fmaxf(s1, m);
    s2 = fmaxf(s2, m2);
}

// ---------------- 1) patch embedding + L2 norm -> bf16 ----------------
// w staged in dynamic smem (coalesced load, stride-113 -> conflict-free LDS).
__global__ void embed_kernel(const float* __restrict__ fm, const float* __restrict__ w) {
    extern __shared__ float dyn[];
    float* ws  = dyn;                    // [128][113] padded weights
    float* xs  = ws + DD * WSTR;         // [8][112]
    float* es  = xs + 8 * C_INN;         // [8][128]
    float* inv = es + 8 * DD;            // [8]
    const int t = threadIdx.x;           // 128 threads
    const int qbase = blockIdx.x * 8;

    // coalesced weight load into padded smem
    for (int idx = t; idx < DD * C_INN; idx += 128) {
        int d = idx / C_INN, c = idx % C_INN;
        ws[d * WSTR + c] = w[idx];
    }
    for (int idx = t; idx < 8 * C_INN; idx += 128) {
        int qi = idx / C_INN, c = idx % C_INN;
        int q = qbase + qi;
        int b = q >> 8, p = q & 255;
        int y = p >> 4, x = p & 15;
        xs[qi * C_INN + c] = fm[((b * C_INN + c) * HH + y) * WWW + x];
    }
    __syncthreads();

    const int d = t;
    float acc[8];
#pragma unroll
    for (int qi = 0; qi < 8; qi++) acc[qi] = 0.f;
    for (int c = 0; c < C_INN; c++) {
        float wv = ws[d * WSTR + c];     // conflict-free: 17*d mod 32 full cycle
#pragma unroll
        for (int qi = 0; qi < 8; qi++) acc[qi] += xs[qi * C_INN + c] * wv;
    }
#pragma unroll
    for (int qi = 0; qi < 8; qi++) es[qi * DD + d] = acc[qi];
    __syncthreads();

    if (t < 8) {
        float ss = 0.f;
        for (int dd2 = 0; dd2 < DD; dd2++) { float v = es[t * DD + dd2]; ss += v * v; }
        inv[t] = 1.0f / fmaxf(sqrtf(ss), 1e-12f);
    }
    __syncthreads();
#pragma unroll
    for (int qi = 0; qi < 8; qi++)
        g_q[(qbase + qi) * DD + t] = __float2bfloat16(es[qi * DD + t] * inv[qi]);
}

// ---------------- 2) bank L2 norm -> bf16 (zero padding rows) ----------------
__global__ void bank_norm_kernel(const float* __restrict__ bank) {
    const int wid = threadIdx.x >> 5, lane = threadIdx.x & 31;
    const long long row = (long long)blockIdx.x * 8 + wid;
    if (row >= NB_PAD) return;
    __nv_bfloat162* dst = (__nv_bfloat162*)(g_bank + (size_t)row * DD);
    if (row < N_BANK) {
        float4 v = ((const float4*)(bank + (size_t)row * DD))[lane];
        float ss = v.x * v.x + v.y * v.y + v.z * v.z + v.w * v.w;
#pragma unroll
        for (int m = 16; m > 0; m >>= 1) ss += __shfl_xor_sync(0xffffffffu, ss, m);
        float inv = 1.0f / fmaxf(sqrtf(ss), 1e-12f);
        dst[lane * 2]     = __floats2bfloat162_rn(v.x * inv, v.y * inv);
        dst[lane * 2 + 1] = __floats2bfloat162_rn(v.z * inv, v.w * inv);
    } else {
        dst[lane * 2]     = __floats2bfloat162_rn(0.f, 0.f);
        dst[lane * 2 + 1] = __floats2bfloat162_rn(0.f, 0.f);
    }
}

// ---------------- 3) fused GEMM + streaming top-3 (R6 core, unchanged) ----------------
// grid (NS, QT), 256 threads = 8 warps (4 M-strips x 2 N-halves), 2 CTAs/SM.
// 2-stage cp.async pipeline on B tiles; per-lane running top-3 per fragment
// row-group, screened by a max-tree; cross-lane merge once at the end.
__global__ void __launch_bounds__(256, 2) sim_topk_kernel() {
    extern __shared__ __align__(16) __nv_bfloat16 smem[];
    __nv_bfloat16* q_sm = smem;                 // [128][136]
    __nv_bfloat16* b_sm = smem + TILE_SM;       // 2 stages of [128][136]

    const int t = threadIdx.x;
    const int lane = t & 31, w = t >> 5;
    const int slice = blockIdx.x, qt = blockIdx.y;
    const int wm = (w >> 1) * 32;       // warp M base (queries)
    const int wn = (w & 1) * 64;        // warp N base (bank cols)
    const int tb = slice * PER_SL;
    const int nt = min(tb + PER_SL, N_TILES) - tb;

    // A (query) tile -> smem, once
    {
        const uint4* src = (const uint4*)(g_q + (size_t)qt * QTILE * DD);
#pragma unroll
        for (int it = 0; it < 8; it++) {
            int u = t + it * 256;
            int row = u >> 4, c16 = u & 15;
            *(uint4*)(q_sm + row * LDSS + c16 * 8) = src[u];
        }
    }

    const unsigned b_base = (unsigned)__cvta_generic_to_shared(b_sm);

    // issue one B tile into a stage via cp.async (8 x 16B per thread)
    auto issue_b = [&](int stage, int tile) {
        const char* src = (const char*)(g_bank + (size_t)tile * QTILE * DD);
        const unsigned dst0 = b_base + stage * (TILE_SM * 2);
#pragma unroll
        for (int it = 0; it < 8; it++) {
            int u = t + it * 256;
            int row = u >> 4, c16 = u & 15;
            unsigned dst = dst0 + row * (LDSS * 2) + c16 * 16;
            asm volatile("cp.async.cg.shared.global [%0], [%1], 16;\n"
                         :: "r"(dst), "l"(src + (size_t)u * 16));
        }
    };

    // prologue: tile 0 -> stage 0
    issue_b(0, tb);
    asm volatile("cp.async.commit_group;\n" ::: "memory");

    float run[4][3];
#pragma unroll
    for (int i = 0; i < 4; i++) { run[i][0] = -3.f; run[i][1] = -3.f; run[i][2] = -3.f; }

    // per-lane ldmatrix address components (validated in R3/R6)
    const int a_row = (lane & 15);
    const int a_coff = (lane >= 16) ? 8 : 0;
    const int b_row = (lane & 7) + ((lane >= 16) ? 8 : 0);
    const int b_coff = (lane & 8) ? 8 : 0;

    for (int i = 0; i < nt; i++) {
        if (i + 1 < nt) issue_b((i + 1) & 1, tb + i + 1);
        asm volatile("cp.async.commit_group;\n" ::: "memory");
        asm volatile("cp.async.wait_group %0;\n" :: "n"(1) : "memory");
        __syncthreads();   // tile i visible to all; previous stage reads done

        const __nv_bfloat16* bs = b_sm + (i & 1) * TILE_SM;

        float acc[2][8][4];
#pragma unroll
        for (int a = 0; a < 2; a++)
#pragma unroll
            for (int j = 0; j < 8; j++)
#pragma unroll
                for (int r = 0; r < 4; r++) acc[a][j][r] = 0.f;

#pragma unroll
        for (int ks = 0; ks < 8; ks++) {
            const int kb = ks * 16;
            unsigned a[2][4];
#pragma unroll
            for (int ai = 0; ai < 2; ai++) {
                unsigned addr = (unsigned)__cvta_generic_to_shared(
                    q_sm + (wm + ai * 16 + a_row) * LDSS + kb + a_coff);
                asm volatile(
                    "ldmatrix.sync.aligned.m8n8.x4.shared.b16 {%0,%1,%2,%3}, [%4];\n"
                    : "=r"(a[ai][0]), "=r"(a[ai][1]), "=r"(a[ai][2]), "=r"(a[ai][3])
                    : "r"(addr));
            }
#pragma unroll
            for (int jp = 0; jp < 4; jp++) {
                unsigned b0, b1, b2, b3;
                unsigned addr = (unsigned)__cvta_generic_to_shared(
                    bs + (wn + jp * 16 + b_row) * LDSS + kb + b_coff);
                asm volatile(
                    "ldmatrix.sync.aligned.m8n8.x4.shared.b16 {%0,%1,%2,%3}, [%4];\n"
                    : "=r"(b0), "=r"(b1), "=r"(b2), "=r"(b3)
                    : "r"(addr));
#pragma unroll
                for (int ai = 0; ai < 2; ai++) {
                    asm volatile(
                        "mma.sync.aligned.m16n8k16.row.col.f32.bf16.bf16.f32 "
                        "{%0,%1,%2,%3},{%4,%5,%6,%7},{%8,%9},{%0,%1,%2,%3};\n"
                        : "+f"(acc[ai][2 * jp][0]), "+f"(acc[ai][2 * jp][1]),
                          "+f"(acc[ai][2 * jp][2]), "+f"(acc[ai][2 * jp][3])
                        : "r"(a[ai][0]), "r"(a[ai][1]), "r"(a[ai][2]), "r"(a[ai][3]),
                          "r"(b0), "r"(b1));
                    asm volatile(
                        "mma.sync.aligned.m16n8k16.row.col.f32.bf16.bf16.f32 "
                        "{%0,%1,%2,%3},{%4,%5,%6,%7},{%8,%9},{%0,%1,%2,%3};\n"
                        : "+f"(acc[ai][2 * jp + 1][0]), "+f"(acc[ai][2 * jp + 1][1]),
                          "+f"(acc[ai][2 * jp + 1][2]), "+f"(acc[ai][2 * jp + 1][3])
                        : "r"(a[ai][0]), "r"(a[ai][1]), "r"(a[ai][2]), "r"(a[ai][3]),
                          "r"(b2), "r"(b3));
                }
            }
        }

        // screened per-lane top-3: max-tree over the 16 values of each
        // (M-half, row-half) group; full insert only if it can change top-3.
#pragma unroll
        for (int i2 = 0; i2 < 2; i2++) {
#pragma unroll
            for (int hi = 0; hi < 2; hi++) {
                float m[8];
#pragma unroll
                for (int j = 0; j < 8; j++)
                    m[j] = fmaxf(acc[i2][j][2 * hi], acc[i2][j][2 * hi + 1]);
#pragma unroll
                for (int s = 4; s > 0; s >>= 1)
#pragma unroll
                    for (int j = 0; j < s; j++) m[j] = fmaxf(m[j], m[j + s]);
                const int idx = i2 * 2 + hi;
                if (m[0] > run[idx][2]) {
#pragma unroll
                    for (int j = 0; j < 8; j++) {
                        ins3(acc[i2][j][2 * hi],     run[idx][0], run[idx][1], run[idx][2]);
                        ins3(acc[i2][j][2 * hi + 1], run[idx][0], run[idx][1], run[idx][2]);
                    }
                }
            }
        }
        __syncthreads();   // all reads of stage (i&1) done before next overwrite
    }

    // ---- final merge: lanes sharing a row (xor 1,2), then the two N-halves ----
    float* fsm = (float*)smem;   // reuse smem as [128 rows][2 halves][3] staging
#pragma unroll
    for (int idx = 0; idx < 4; idx++) {
        float s0 = run[idx][0], s1 = run[idx][1], s2 = run[idx][2];
#pragma unroll
        for (int m = 1; m <= 2; m <<= 1) {
            float o0 = __shfl_xor_sync(0xffffffffu, s0, m);
            float o1 = __shfl_xor_sync(0xffffffffu, s1, m);
            float o2 = __shfl_xor_sync(0xffffffffu, s2, m);
            ins3(o0, s0, s1, s2); ins3(o1, s0, s1, s2); ins3(o2, s0, s1, s2);
        }
        if ((lane & 3) == 0) {
            int row = wm + (idx >> 1) * 16 + (lane >> 2) + ((idx & 1) << 3);
            fsm[(row * 2 + (w & 1)) * 3 + 0] = s0;
            fsm[(row * 2 + (w & 1)) * 3 + 1] = s1;
            fsm[(row * 2 + (w & 1)) * 3 + 2] = s2;
        }
    }
    __syncthreads();
    if (t < QTILE) {
        float s0 = fsm[(t * 2) * 3 + 0], s1 = fsm[(t * 2) * 3 + 1], s2 = fsm[(t * 2) * 3 + 2];
        ins3(fsm[(t * 2 + 1) * 3 + 0], s0, s1, s2);
        ins3(fsm[(t * 2 + 1) * 3 + 1], s0, s1, s2);
        ins3(fsm[(t * 2 + 1) * 3 + 2], s0, s1, s2);
        float* dst = g_partial + (((size_t)qt * NS + slice) * QTILE + t) * 3;
        dst[0] = s0; dst[1] = s1; dst[2] = s2;
    }
}

// ---------------- 4) merge slices, per-query dist, per-batch top-8 mean ----------------
__global__ void finalize_kernel(float* __restrict__ out) {
    __shared__ float cand[64];
    const int b = blockIdx.x, t = threadIdx.x;     // 256 threads = 256 patches of batch b
    const int lane = t & 31, wid = t >> 5;
    const int q = b * 256 + t;
    const int qt = q >> 7, row = q & 127;
    float s0 = -3.f, s1 = -3.f, s2 = -3.f;
    for (int s = 0; s < NS; s++) {
        const float* p = g_partial + (((size_t)qt * NS + s) * QTILE + row) * 3;
        ins3(p[0], s0, s1, s2); ins3(p[1], s0, s1, s2); ins3(p[2], s0, s1, s2);
    }
    float d0 = sqrtf(fmaxf(2.f - 2.f * s0, 0.f));
    float d1 = sqrtf(fmaxf(2.f - 2.f * s1, 0.f));
    float d2 = sqrtf(fmaxf(2.f - 2.f * s2, 0.f));
    float x = (d0 + d1 + d2) * (1.f / 3.f);

    // stage 1: per-warp top-8 by knockout max-reduction -> 64 candidates
    for (int it = 0; it < 8; it++) {
        float mx = x;
        for (int m = 16; m > 0; m >>= 1)
            mx = fmaxf(mx, __shfl_xor_sync(0xffffffffu, mx, m));
        unsigned bal = __ballot_sync(0xffffffffu, x == mx);
        if (lane == 0) cand[wid * 8 + it] = mx;
        if (lane == (int)(__ffs(bal) - 1)) x = -1e30f;
    }
    __syncthreads();

    // stage 2: warp 0 knockout over the 64 candidates (2 regs/lane, parallel)
    if (wid == 0) {
        float v0 = cand[lane], v1 = cand[32 + lane];
        float sum = 0.f;
#pragma unroll
        for (int it = 0; it < 8; it++) {
            float lm = fmaxf(v0, v1);
            float mx = lm;
#pragma unroll
            for (int m = 16; m > 0; m >>= 1)
                mx = fmaxf(mx, __shfl_xor_sync(0xffffffffu, mx, m));
            sum += mx;
            unsigned bal = __ballot_sync(0xffffffffu, lm == mx);
            if (lane == (int)(__ffs(bal) - 1)) {
                if (v0 == mx) v0 = -1e30f; else v1 = -1e30f;
            }
        }
        if (lane == 0) out[b] = sum * 0.125f;   // k = ceil(256*0.03) = 8
    }
}

// ---------------- launch ----------------
extern "C" void kernel_launch(void* const* d_in, const int* in_sizes, int n_in,
                              void* d_out, int out_size) {
    const float* fm   = (const float*)d_in[0];  // [8,112,16,16]
    const float* w    = (const float*)d_in[1];  // [128,112]
    const float* bank = (const float*)d_in[2];  // [200000,128]
    float* out = (float*)d_out;                 // [8]

    const int embed_smem = (DD * WSTR + 8 * C_INN + 8 * DD + 8) * (int)sizeof(float);
    cudaFuncSetAttribute(embed_kernel,
                         cudaFuncAttributeMaxDynamicSharedMemorySize, embed_smem);
    embed_kernel<<<QTOT / 8, 128, embed_smem>>>(fm, w);
    bank_norm_kernel<<<NB_PAD / 8, 256>>>(bank);

    const int smem_bytes = 3 * TILE_SM * (int)sizeof(__nv_bfloat16);  // 104448
    cudaFuncSetAttribute(sim_topk_kernel,
                         cudaFuncAttributeMaxDynamicSharedMemorySize, smem_bytes);
    dim3 grid(NS, QT);
    sim_topk_kernel<<<grid, 256, smem_bytes>>>();

    finalize_kernel<<<BQ, 256>>>(out);
}

// round 16
// speedup vs baseline: 1.1938x; 1.0105x over previous
#include <cuda_runtime.h>
#include <cuda_bf16.h>
#include <stdint.h>
#include <math.h>

// ---------------- problem constants ----------------
#define BQ      8
#define C_INN   112
#define HH      16
#define WWW     16
#define DD      128
#define N_BANK  200000
#define NB_PAD  200064          // 1563 * 128 (pad rows zeroed -> sim 0, never top-3)
#define N_TILES 1563
#define NS      18              // bank slices; 16*18 = 288 CTAs = 2 per SM
#define PER_SL  87              // ceil(1563/18)
#define QTOT    2048
#define QT      16
#define QTILE   128
#define LDSS    136             // smem row stride in bf16 (272B -> conflict-free ldmatrix)
#define TILE_SM (QTILE * LDSS)  // bf16 elements per smem tile (34816 B)
#define WSTR    113             // padded smem stride for the weight matrix

// ---------------- device scratch (no allocs allowed) ----------------
__device__ __nv_bfloat16 g_bank[(size_t)NB_PAD * DD];   // 51.2 MB normalized bf16 bank
__device__ __nv_bfloat16 g_q[QTOT * DD];                // normalized bf16 queries
__device__ float g_partial[QT * NS * QTILE * 3];        // per-(qtile,slice,row) top-3 sims

// ---------------- helpers ----------------
__device__ __forceinline__ void ins3(float v, float& s0, float& s1, float& s2) {
    float m  = fminf(s0, v);
    s0 = fmaxf(s0, v);
    float m2 = fminf(s1, m);
    s1 = fmaxf(s1, m);
    s2 = fmaxf(s2, m2);
}

// ---------------- 1) patch embedding + L2 norm -> bf16 ----------------
// w staged in dynamic smem (coalesced load, stride-113 -> conflict-free LDS).
__global__ void embed_kernel(const float* __restrict__ fm, const float* __restrict__ w) {
    extern __shared__ float dyn[];
    float* ws  = dyn;                    // [128][113] padded weights
    float* xs  = ws + DD * WSTR;         // [8][112]
    float* es  = xs + 8 * C_INN;         // [8][128]
    float* inv = es + 8 * DD;            // [8]
    const int t = threadIdx.x;           // 128 threads
    const int qbase = blockIdx.x * 8;

    // coalesced weight load into padded smem
    for (int idx = t; idx < DD * C_INN; idx += 128) {
        int d = idx / C_INN, c = idx % C_INN;
        ws[d * WSTR + c] = w[idx];
    }
    for (int idx = t; idx < 8 * C_INN; idx += 128) {
        int qi = idx / C_INN, c = idx % C_INN;
        int q = qbase + qi;
        int b = q >> 8, p = q & 255;
        int y = p >> 4, x = p & 15;
        xs[qi * C_INN + c] = fm[((b * C_INN + c) * HH + y) * WWW + x];
    }
    __syncthreads();

    const int d = t;
    float acc[8];
#pragma unroll
    for (int qi = 0; qi < 8; qi++) acc[qi] = 0.f;
    for (int c = 0; c < C_INN; c++) {
        float wv = ws[d * WSTR + c];     // conflict-free: 17*d mod 32 full cycle
#pragma unroll
        for (int qi = 0; qi < 8; qi++) acc[qi] += xs[qi * C_INN + c] * wv;
    }
#pragma unroll
    for (int qi = 0; qi < 8; qi++) es[qi * DD + d] = acc[qi];
    __syncthreads();

    if (t < 8) {
        float ss = 0.f;
        for (int dd2 = 0; dd2 < DD; dd2++) { float v = es[t * DD + dd2]; ss += v * v; }
        inv[t] = 1.0f / fmaxf(sqrtf(ss), 1e-12f);
    }
    __syncthreads();
#pragma unroll
    for (int qi = 0; qi < 8; qi++)
        g_q[(qbase + qi) * DD + t] = __float2bfloat16(es[qi * DD + t] * inv[qi]);
}

// ---------------- 2) bank L2 norm -> bf16, MLP=8 DRAM-bound version ----------------
// 512 threads = 16 warps; each warp handles 8 rows (8 independent LDG.128/lane
// in flight, interleaved shfl chains, coalesced 8B store per lane per row).
// Output is bit-identical to the warp-per-row version (same math per row).
__global__ void __launch_bounds__(512) bank_norm_kernel(const float* __restrict__ bank) {
    const int wid = threadIdx.x >> 5, lane = threadIdx.x & 31;
    const int row0 = blockIdx.x * 128 + wid * 8;

    float4 v[8];
    float ss[8];
#pragma unroll
    for (int r = 0; r < 8; r++) {
        const int row = row0 + r;
        if (row < N_BANK) {
            v[r] = ((const float4*)(bank + (size_t)row * DD))[lane];
        } else {
            v[r] = make_float4(0.f, 0.f, 0.f, 0.f);
        }
    }
#pragma unroll
    for (int r = 0; r < 8; r++)
        ss[r] = v[r].x * v[r].x + v[r].y * v[r].y + v[r].z * v[r].z + v[r].w * v[r].w;
#pragma unroll
    for (int m = 16; m > 0; m >>= 1) {
#pragma unroll
        for (int r = 0; r < 8; r++)
            ss[r] += __shfl_xor_sync(0xffffffffu, ss[r], m);
    }
#pragma unroll
    for (int r = 0; r < 8; r++) {
        float inv = 1.0f / fmaxf(sqrtf(ss[r]), 1e-12f);   // pad rows: 0 stays 0
        __nv_bfloat162 lo = __floats2bfloat162_rn(v[r].x * inv, v[r].y * inv);
        __nv_bfloat162 hi = __floats2bfloat162_rn(v[r].z * inv, v[r].w * inv);
        uint2 o;
        o.x = *(unsigned*)&lo;
        o.y = *(unsigned*)&hi;
        *(uint2*)(g_bank + (size_t)(row0 + r) * DD + lane * 4) = o;
    }
}

// ---------------- 3) fused GEMM + streaming top-3 (R6 core, unchanged) ----------------
// grid (NS, QT), 256 threads = 8 warps (4 M-strips x 2 N-halves), 2 CTAs/SM.
// 2-stage cp.async pipeline on B tiles; per-lane running top-3 per fragment
// row-group, screened by a max-tree; cross-lane merge once at the end.
__global__ void __launch_bounds__(256, 2) sim_topk_kernel() {
    extern __shared__ __align__(16) __nv_bfloat16 smem[];
    __nv_bfloat16* q_sm = smem;                 // [128][136]
    __nv_bfloat16* b_sm = smem + TILE_SM;       // 2 stages of [128][136]

    const int t = threadIdx.x;
    const int lane = t & 31, w = t >> 5;
    const int slice = blockIdx.x, qt = blockIdx.y;
    const int wm = (w >> 1) * 32;       // warp M base (queries)
    const int wn = (w & 1) * 64;        // warp N base (bank cols)
    const int tb = slice * PER_SL;
    const int nt = min(tb + PER_SL, N_TILES) - tb;

    // A (query) tile -> smem, once
    {
        const uint4* src = (const uint4*)(g_q + (size_t)qt * QTILE * DD);
#pragma unroll
        for (int it = 0; it < 8; it++) {
            int u = t + it * 256;
            int row = u >> 4, c16 = u & 15;
            *(uint4*)(q_sm + row * LDSS + c16 * 8) = src[u];
        }
    }

    const unsigned b_base = (unsigned)__cvta_generic_to_shared(b_sm);

    // issue one B tile into a stage via cp.async (8 x 16B per thread)
    auto issue_b = [&](int stage, int tile) {
        const char* src = (const char*)(g_bank + (size_t)tile * QTILE * DD);
        const unsigned dst0 = b_base + stage * (TILE_SM * 2);
#pragma unroll
        for (int it = 0; it < 8; it++) {
            int u = t + it * 256;
            int row = u >> 4, c16 = u & 15;
            unsigned dst = dst0 + row * (LDSS * 2) + c16 * 16;
            asm volatile("cp.async.cg.shared.global [%0], [%1], 16;\n"
                         :: "r"(dst), "l"(src + (size_t)u * 16));
        }
    };

    // prologue: tile 0 -> stage 0
    issue_b(0, tb);
    asm volatile("cp.async.commit_group;\n" ::: "memory");

    float run[4][3];
#pragma unroll
    for (int i = 0; i < 4; i++) { run[i][0] = -3.f; run[i][1] = -3.f; run[i][2] = -3.f; }

    // per-lane ldmatrix address components (validated in R3/R6)
    const int a_row = (lane & 15);
    const int a_coff = (lane >= 16) ? 8 : 0;
    const int b_row = (lane & 7) + ((lane >= 16) ? 8 : 0);
    const int b_coff = (lane & 8) ? 8 : 0;

    for (int i = 0; i < nt; i++) {
        if (i + 1 < nt) issue_b((i + 1) & 1, tb + i + 1);
        asm volatile("cp.async.commit_group;\n" ::: "memory");
        asm volatile("cp.async.wait_group %0;\n" :: "n"(1) : "memory");
        __syncthreads();   // tile i visible to all; previous stage reads done

        const __nv_bfloat16* bs = b_sm + (i & 1) * TILE_SM;

        float acc[2][8][4];
#pragma unroll
        for (int a = 0; a < 2; a++)
#pragma unroll
            for (int j = 0; j < 8; j++)
#pragma unroll
                for (int r = 0; r < 4; r++) acc[a][j][r] = 0.f;

#pragma unroll
        for (int ks = 0; ks < 8; ks++) {
            const int kb = ks * 16;
            unsigned a[2][4];
#pragma unroll
            for (int ai = 0; ai < 2; ai++) {
                unsigned addr = (unsigned)__cvta_generic_to_shared(
                    q_sm + (wm + ai * 16 + a_row) * LDSS + kb + a_coff);
                asm volatile(
                    "ldmatrix.sync.aligned.m8n8.x4.shared.b16 {%0,%1,%2,%3}, [%4];\n"
                    : "=r"(a[ai][0]), "=r"(a[ai][1]), "=r"(a[ai][2]), "=r"(a[ai][3])
                    : "r"(addr));
            }
#pragma unroll
            for (int jp = 0; jp < 4; jp++) {
                unsigned b0, b1, b2, b3;
                unsigned addr = (unsigned)__cvta_generic_to_shared(
                    bs + (wn + jp * 16 + b_row) * LDSS + kb + b_coff);
                asm volatile(
                    "ldmatrix.sync.aligned.m8n8.x4.shared.b16 {%0,%1,%2,%3}, [%4];\n"
                    : "=r"(b0), "=r"(b1), "=r"(b2), "=r"(b3)
                    : "r"(addr));
#pragma unroll
                for (int ai = 0; ai < 2; ai++) {
                    asm volatile(
                        "mma.sync.aligned.m16n8k16.row.col.f32.bf16.bf16.f32 "
                        "{%0,%1,%2,%3},{%4,%5,%6,%7},{%8,%9},{%0,%1,%2,%3};\n"
                        : "+f"(acc[ai][2 * jp][0]), "+f"(acc[ai][2 * jp][1]),
                          "+f"(acc[ai][2 * jp][2]), "+f"(acc[ai][2 * jp][3])
                        : "r"(a[ai][0]), "r"(a[ai][1]), "r"(a[ai][2]), "r"(a[ai][3]),
                          "r"(b0), "r"(b1));
                    asm volatile(
                        "mma.sync.aligned.m16n8k16.row.col.f32.bf16.bf16.f32 "
                        "{%0,%1,%2,%3},{%4,%5,%6,%7},{%8,%9},{%0,%1,%2,%3};\n"
                        : "+f"(acc[ai][2 * jp + 1][0]), "+f"(acc[ai][2 * jp + 1][1]),
                          "+f"(acc[ai][2 * jp + 1][2]), "+f"(acc[ai][2 * jp + 1][3])
                        : "r"(a[ai][0]), "r"(a[ai][1]), "r"(a[ai][2]), "r"(a[ai][3]),
                          "r"(b2), "r"(b3));
                }
            }
        }

        // screened per-lane top-3: max-tree over the 16 values of each
        // (M-half, row-half) group; full insert only if it can change top-3.
#pragma unroll
        for (int i2 = 0; i2 < 2; i2++) {
#pragma unroll
            for (int hi = 0; hi < 2; hi++) {
                float m[8];
#pragma unroll
                for (int j = 0; j < 8; j++)
                    m[j] = fmaxf(acc[i2][j][2 * hi], acc[i2][j][2 * hi + 1]);
#pragma unroll
                for (int s = 4; s > 0; s >>= 1)
#pragma unroll
                    for (int j = 0; j < s; j++) m[j] = fmaxf(m[j], m[j + s]);
                const int idx = i2 * 2 + hi;
                if (m[0] > run[idx][2]) {
#pragma unroll
                    for (int j = 0; j < 8; j++) {
                        ins3(acc[i2][j][2 * hi],     run[idx][0], run[idx][1], run[idx][2]);
                        ins3(acc[i2][j][2 * hi + 1], run[idx][0], run[idx][1], run[idx][2]);
                    }
                }
            }
        }
        __syncthreads();   // all reads of stage (i&1) done before next overwrite
    }

    // ---- final merge: lanes sharing a row (xor 1,2), then the two N-halves ----
    float* fsm = (float*)smem;   // reuse smem as [128 rows][2 halves][3] staging
#pragma unroll
    for (int idx = 0; idx < 4; idx++) {
        float s0 = run[idx][0], s1 = run[idx][1], s2 = run[idx][2];
#pragma unroll
        for (int m = 1; m <= 2; m <<= 1) {
            float o0 = __shfl_xor_sync(0xffffffffu, s0, m);
            float o1 = __shfl_xor_sync(0xffffffffu, s1, m);
            float o2 = __shfl_xor_sync(0xffffffffu, s2, m);
            ins3(o0, s0, s1, s2); ins3(o1, s0, s1, s2); ins3(o2, s0, s1, s2);
        }
        if ((lane & 3) == 0) {
            int row = wm + (idx >> 1) * 16 + (lane >> 2) + ((idx & 1) << 3);
            fsm[(row * 2 + (w & 1)) * 3 + 0] = s0;
            fsm[(row * 2 + (w & 1)) * 3 + 1] = s1;
            fsm[(row * 2 + (w & 1)) * 3 + 2] = s2;
        }
    }
    __syncthreads();
    if (t < QTILE) {
        float s0 = fsm[(t * 2) * 3 + 0], s1 = fsm[(t * 2) * 3 + 1], s2 = fsm[(t * 2) * 3 + 2];
        ins3(fsm[(t * 2 + 1) * 3 + 0], s0, s1, s2);
        ins3(fsm[(t * 2 + 1) * 3 + 1], s0, s1, s2);
        ins3(fsm[(t * 2 + 1) * 3 + 2], s0, s1, s2);
        float* dst = g_partial + (((size_t)qt * NS + slice) * QTILE + t) * 3;
        dst[0] = s0; dst[1] = s1; dst[2] = s2;
    }
}

// ---------------- 4) merge slices, per-query dist, per-batch top-8 mean ----------------
__global__ void finalize_kernel(float* __restrict__ out) {
    __shared__ float cand[64];
    const int b = blockIdx.x, t = threadIdx.x;     // 256 threads = 256 patches of batch b
    const int lane = t & 31, wid = t >> 5;
    const int q = b * 256 + t;
    const int qt = q >> 7, row = q & 127;
    float s0 = -3.f, s1 = -3.f, s2 = -3.f;
    for (int s = 0; s < NS; s++) {
        const float* p = g_partial + (((size_t)qt * NS + s) * QTILE + row) * 3;
        ins3(p[0], s0, s1, s2); ins3(p[1], s0, s1, s2); ins3(p[2], s0, s1, s2);
    }
    float d0 = sqrtf(fmaxf(2.f - 2.f * s0, 0.f));
    float d1 = sqrtf(fmaxf(2.f - 2.f * s1, 0.f));
    float d2 = sqrtf(fmaxf(2.f - 2.f * s2, 0.f));
    float x = (d0 + d1 + d2) * (1.f / 3.f);

    // stage 1: per-warp top-8 by knockout max-reduction -> 64 candidates
    for (int it = 0; it < 8; it++) {
        float mx = x;
        for (int m = 16; m > 0; m >>= 1)
            mx = fmaxf(mx, __shfl_xor_sync(0xffffffffu, mx, m));
        unsigned bal = __ballot_sync(0xffffffffu, x == mx);
        if (lane == 0) cand[wid * 8 + it] = mx;
        if (lane == (int)(__ffs(bal) - 1)) x = -1e30f;
    }
    __syncthreads();

    // stage 2: warp 0 knockout over the 64 candidates (2 regs/lane, parallel)
    if (wid == 0) {
        float v0 = cand[lane], v1 = cand[32 + lane];
        float sum = 0.f;
#pragma unroll
        for (int it = 0; it < 8; it++) {
            float lm = fmaxf(v0, v1);
            float mx = lm;
#pragma unroll
            for (int m = 16; m > 0; m >>= 1)
                mx = fmaxf(mx, __shfl_xor_sync(0xffffffffu, mx, m));
            sum += mx;
            unsigned bal = __ballot_sync(0xffffffffu, lm == mx);
            if (lane == (int)(__ffs(bal) - 1)) {
                if (v0 == mx) v0 = -1e30f; else v1 = -1e30f;
            }
        }
        if (lane == 0) out[b] = sum * 0.125f;   // k = ceil(256*0.03) = 8
    }
}

// ---------------- launch ----------------
extern "C" void kernel_launch(void* const* d_in, const int* in_sizes, int n_in,
                              void* d_out, int out_size) {
    const float* fm   = (const float*)d_in[0];  // [8,112,16,16]
    const float* w    = (const float*)d_in[1];  // [128,112]
    const float* bank = (const float*)d_in[2];  // [200000,128]
    float* out = (float*)d_out;                 // [8]

    const int embed_smem = (DD * WSTR + 8 * C_INN + 8 * DD + 8) * (int)sizeof(float);
    cudaFuncSetAttribute(embed_kernel,
                         cudaFuncAttributeMaxDynamicSharedMemorySize, embed_smem);
    embed_kernel<<<QTOT / 8, 128, embed_smem>>>(fm, w);
    bank_norm_kernel<<<NB_PAD / 128, 512>>>(bank);

    const int smem_bytes = 3 * TILE_SM * (int)sizeof(__nv_bfloat16);  // 104448
    cudaFuncSetAttribute(sim_topk_kernel,
                         cudaFuncAttributeMaxDynamicSharedMemorySize, smem_bytes);
    dim3 grid(NS, QT);
    sim_topk_kernel<<<grid, 256, smem_bytes>>>();

    finalize_kernel<<<BQ, 256>>>(out);
}

// round 17
// speedup vs baseline: 1.1990x; 1.0044x over previous
#include <cuda_runtime.h>
#include <cuda_bf16.h>
#include <stdint.h>
#include <math.h>

// ---------------- problem constants ----------------
#define BQ      8
#define C_INN   112
#define HH      16
#define WWW     16
#define DD      128
#define N_BANK  200000
#define NB_PAD  200064          // 1563 * 128 (pad rows zeroed -> sim 0, never top-3)
#define N_TILES 1563
#define NS      37              // bank slices; 16*37 = 592 CTAs = exactly 2 waves @2/SM
#define PER_SL  43              // ceil(1563/37); last slice 15 tiles
#define QTOT    2048
#define QT      16
#define QTILE   128
#define LDSS    136             // smem row stride in bf16 (272B -> conflict-free ldmatrix)
#define TILE_SM (QTILE * LDSS)  // bf16 elements per smem tile (34816 B)
#define WSTR    113             // padded smem stride for the weight matrix

// ---------------- device scratch (no allocs allowed) ----------------
__device__ __nv_bfloat16 g_bank[(size_t)NB_PAD * DD];   // 51.2 MB normalized bf16 bank
__device__ __nv_bfloat16 g_q[QTOT * DD];                // normalized bf16 queries
__device__ float g_partial[QT * NS * QTILE * 3];        // per-(qtile,slice,row) top-3 sims

// ---------------- helpers ----------------
__device__ __forceinline__ void ins3(float v, float& s0, float& s1, float& s2) {
    float m  = fminf(s0, v);
    s0 = fmaxf(s0, v);
    float m2 = fminf(s1, m);
    s1 = fmaxf(s1, m);
    s2 = fmaxf(s2, m2);
}

// ---------------- 1) patch embedding + L2 norm -> bf16 ----------------
// w staged in dynamic smem (coalesced load, stride-113 -> conflict-free LDS).
__global__ void embed_kernel(const float* __restrict__ fm, const float* __restrict__ w) {
    extern __shared__ float dyn[];
    float* ws  = dyn;                    // [128][113] padded weights
    float* xs  = ws + DD * WSTR;         // [8][112]
    float* es  = xs + 8 * C_INN;         // [8][128]
    float* inv = es + 8 * DD;            // [8]
    const int t = threadIdx.x;           // 128 threads
    const int qbase = blockIdx.x * 8;

    // coalesced weight load into padded smem
    for (int idx = t; idx < DD * C_INN; idx += 128) {
        int d = idx / C_INN, c = idx % C_INN;
        ws[d * WSTR + c] = w[idx];
    }
    for (int idx = t; idx < 8 * C_INN; idx += 128) {
        int qi = idx / C_INN, c = idx % C_INN;
        int q = qbase + qi;
        int b = q >> 8, p = q & 255;
        int y = p >> 4, x = p & 15;
        xs[qi * C_INN + c] = fm[((b * C_INN + c) * HH + y) * WWW + x];
    }
    __syncthreads();

    const int d = t;
    float acc[8];
#pragma unroll
    for (int qi = 0; qi < 8; qi++) acc[qi] = 0.f;
    for (int c = 0; c < C_INN; c++) {
        float wv = ws[d * WSTR + c];     // conflict-free: 17*d mod 32 full cycle
#pragma unroll
        for (int qi = 0; qi < 8; qi++) acc[qi] += xs[qi * C_INN + c] * wv;
    }
#pragma unroll
    for (int qi = 0; qi < 8; qi++) es[qi * DD + d] = acc[qi];
    __syncthreads();

    if (t < 8) {
        float ss = 0.f;
        for (int dd2 = 0; dd2 < DD; dd2++) { float v = es[t * DD + dd2]; ss += v * v; }
        inv[t] = 1.0f / fmaxf(sqrtf(ss), 1e-12f);
    }
    __syncthreads();
#pragma unroll
    for (int qi = 0; qi < 8; qi++)
        g_q[(qbase + qi) * DD + t] = __float2bfloat16(es[qi * DD + t] * inv[qi]);
}

// ---------------- 2) bank L2 norm -> bf16, MLP=8 DRAM-bound version ----------------
// 512 threads = 16 warps; each warp handles 8 rows (8 independent LDG.128/lane
// in flight, interleaved shfl chains, coalesced 8B store per lane per row).
__global__ void __launch_bounds__(512) bank_norm_kernel(const float* __restrict__ bank) {
    const int wid = threadIdx.x >> 5, lane = threadIdx.x & 31;
    const int row0 = blockIdx.x * 128 + wid * 8;

    float4 v[8];
    float ss[8];
#pragma unroll
    for (int r = 0; r < 8; r++) {
        const int row = row0 + r;
        if (row < N_BANK) {
            v[r] = ((const float4*)(bank + (size_t)row * DD))[lane];
        } else {
            v[r] = make_float4(0.f, 0.f, 0.f, 0.f);
        }
    }
#pragma unroll
    for (int r = 0; r < 8; r++)
        ss[r] = v[r].x * v[r].x + v[r].y * v[r].y + v[r].z * v[r].z + v[r].w * v[r].w;
#pragma unroll
    for (int m = 16; m > 0; m >>= 1) {
#pragma unroll
        for (int r = 0; r < 8; r++)
            ss[r] += __shfl_xor_sync(0xffffffffu, ss[r], m);
    }
#pragma unroll
    for (int r = 0; r < 8; r++) {
        float inv = 1.0f / fmaxf(sqrtf(ss[r]), 1e-12f);   // pad rows: 0 stays 0
        __nv_bfloat162 lo = __floats2bfloat162_rn(v[r].x * inv, v[r].y * inv);
        __nv_bfloat162 hi = __floats2bfloat162_rn(v[r].z * inv, v[r].w * inv);
        uint2 o;
        o.x = *(unsigned*)&lo;
        o.y = *(unsigned*)&hi;
        *(uint2*)(g_bank + (size_t)(row0 + r) * DD + lane * 4) = o;
    }
}

// ---------------- 3) fused GEMM + streaming top-3 (R6 core, unchanged) ----------------
// grid (NS, QT) = (37, 16) -> 592 CTAs = exactly 2 waves at 2 CTAs/SM on 148 SMs.
// 256 threads = 8 warps (4 M-strips x 2 N-halves). 2-stage cp.async pipeline;
// screened per-lane top-3; cross-lane merge once at the end.
__global__ void __launch_bounds__(256, 2) sim_topk_kernel() {
    extern __shared__ __align__(16) __nv_bfloat16 smem[];
    __nv_bfloat16* q_sm = smem;                 // [128][136]
    __nv_bfloat16* b_sm = smem + TILE_SM;       // 2 stages of [128][136]

    const int t = threadIdx.x;
    const int lane = t & 31, w = t >> 5;
    const int slice = blockIdx.x, qt = blockIdx.y;
    const int wm = (w >> 1) * 32;       // warp M base (queries)
    const int wn = (w & 1) * 64;        // warp N base (bank cols)
    const int tb = slice * PER_SL;
    const int nt = min(tb + PER_SL, N_TILES) - tb;

    // A (query) tile -> smem, once
    {
        const uint4* src = (const uint4*)(g_q + (size_t)qt * QTILE * DD);
#pragma unroll
        for (int it = 0; it < 8; it++) {
            int u = t + it * 256;
            int row = u >> 4, c16 = u & 15;
            *(uint4*)(q_sm + row * LDSS + c16 * 8) = src[u];
        }
    }

    const unsigned b_base = (unsigned)__cvta_generic_to_shared(b_sm);

    // issue one B tile into a stage via cp.async (8 x 16B per thread)
    auto issue_b = [&](int stage, int tile) {
        const char* src = (const char*)(g_bank + (size_t)tile * QTILE * DD);
        const unsigned dst0 = b_base + stage * (TILE_SM * 2);
#pragma unroll
        for (int it = 0; it < 8; it++) {
            int u = t + it * 256;
            int row = u >> 4, c16 = u & 15;
            unsigned dst = dst0 + row * (LDSS * 2) + c16 * 16;
            asm volatile("cp.async.cg.shared.global [%0], [%1], 16;\n"
                         :: "r"(dst), "l"(src + (size_t)u * 16));
        }
    };

    // prologue: tile 0 -> stage 0
    issue_b(0, tb);
    asm volatile("cp.async.commit_group;\n" ::: "memory");

    float run[4][3];
#pragma unroll
    for (int i = 0; i < 4; i++) { run[i][0] = -3.f; run[i][1] = -3.f; run[i][2] = -3.f; }

    // per-lane ldmatrix address components (validated in R3/R6)
    const int a_row = (lane & 15);
    const int a_coff = (lane >= 16) ? 8 : 0;
    const int b_row = (lane & 7) + ((lane >= 16) ? 8 : 0);
    const int b_coff = (lane & 8) ? 8 : 0;

    for (int i = 0; i < nt; i++) {
        if (i + 1 < nt) issue_b((i + 1) & 1, tb + i + 1);
        asm volatile("cp.async.commit_group;\n" ::: "memory");
        asm volatile("cp.async.wait_group %0;\n" :: "n"(1) : "memory");
        __syncthreads();   // tile i visible to all; previous stage reads done

        const __nv_bfloat16* bs = b_sm + (i & 1) * TILE_SM;

        float acc[2][8][4];
#pragma unroll
        for (int a = 0; a < 2; a++)
#pragma unroll
            for (int j = 0; j < 8; j++)
#pragma unroll
                for (int r = 0; r < 4; r++) acc[a][j][r] = 0.f;

#pragma unroll
        for (int ks = 0; ks < 8; ks++) {
            const int kb = ks * 16;
            unsigned a[2][4];
#pragma unroll
            for (int ai = 0; ai < 2; ai++) {
                unsigned addr = (unsigned)__cvta_generic_to_shared(
                    q_sm + (wm + ai * 16 + a_row) * LDSS + kb + a_coff);
                asm volatile(
                    "ldmatrix.sync.aligned.m8n8.x4.shared.b16 {%0,%1,%2,%3}, [%4];\n"
                    : "=r"(a[ai][0]), "=r"(a[ai][1]), "=r"(a[ai][2]), "=r"(a[ai][3])
                    : "r"(addr));
            }
#pragma unroll
            for (int jp = 0; jp < 4; jp++) {
                unsigned b0, b1, b2, b3;
                unsigned addr = (unsigned)__cvta_generic_to_shared(
                    bs + (wn + jp * 16 + b_row) * LDSS + kb + b_coff);
                asm volatile(
                    "ldmatrix.sync.aligned.m8n8.x4.shared.b16 {%0,%1,%2,%3}, [%4];\n"
                    : "=r"(b0), "=r"(b1), "=r"(b2), "=r"(b3)
                    : "r"(addr));
#pragma unroll
                for (int ai = 0; ai < 2; ai++) {
                    asm volatile(
                        "mma.sync.aligned.m16n8k16.row.col.f32.bf16.bf16.f32 "
                        "{%0,%1,%2,%3},{%4,%5,%6,%7},{%8,%9},{%0,%1,%2,%3};\n"
                        : "+f"(acc[ai][2 * jp][0]), "+f"(acc[ai][2 * jp][1]),
                          "+f"(acc[ai][2 * jp][2]), "+f"(acc[ai][2 * jp][3])
                        : "r"(a[ai][0]), "r"(a[ai][1]), "r"(a[ai][2]), "r"(a[ai][3]),
                          "r"(b0), "r"(b1));
                    asm volatile(
                        "mma.sync.aligned.m16n8k16.row.col.f32.bf16.bf16.f32 "
                        "{%0,%1,%2,%3},{%4,%5,%6,%7},{%8,%9},{%0,%1,%2,%3};\n"
                        : "+f"(acc[ai][2 * jp + 1][0]), "+f"(acc[ai][2 * jp + 1][1]),
                          "+f"(acc[ai][2 * jp + 1][2]), "+f"(acc[ai][2 * jp + 1][3])
                        : "r"(a[ai][0]), "r"(a[ai][1]), "r"(a[ai][2]), "r"(a[ai][3]),
                          "r"(b2), "r"(b3));
                }
            }
        }

        // screened per-lane top-3: max-tree over the 16 values of each
        // (M-half, row-half) group; full insert only if it can change top-3.
#pragma unroll
        for (int i2 = 0; i2 < 2; i2++) {
#pragma unroll
            for (int hi = 0; hi < 2; hi++) {
                float m[8];
#pragma unroll
                for (int j = 0; j < 8; j++)
                    m[j] = fmaxf(acc[i2][j][2 * hi], acc[i2][j][2 * hi + 1]);
#pragma unroll
                for (int s = 4; s > 0; s >>= 1)
#pragma unroll
                    for (int j = 0; j < s; j++) m[j] = fmaxf(m[j], m[j + s]);
                const int idx = i2 * 2 + hi;
                if (m[0] > run[idx][2]) {
#pragma unroll
                    for (int j = 0; j < 8; j++) {
                        ins3(acc[i2][j][2 * hi],     run[idx][0], run[idx][1], run[idx][2]);
                        ins3(acc[i2][j][2 * hi + 1], run[idx][0], run[idx][1], run[idx][2]);
                    }
                }
            }
        }
        __syncthreads();   // all reads of stage (i&1) done before next overwrite
    }

    // ---- final merge: lanes sharing a row (xor 1,2), then the two N-halves ----
    float* fsm = (float*)smem;   // reuse smem as [128 rows][2 halves][3] staging
#pragma unroll
    for (int idx = 0; idx < 4; idx++) {
        float s0 = run[idx][0], s1 = run[idx][1], s2 = run[idx][2];
#pragma unroll
        for (int m = 1; m <= 2; m <<= 1) {
            float o0 = __shfl_xor_sync(0xffffffffu, s0, m);
            float o1 = __shfl_xor_sync(0xffffffffu, s1, m);
            float o2 = __shfl_xor_sync(0xffffffffu, s2, m);
            ins3(o0, s0, s1, s2); ins3(o1, s0, s1, s2); ins3(o2, s0, s1, s2);
        }
        if ((lane & 3) == 0) {
            int row = wm + (idx >> 1) * 16 + (lane >> 2) + ((idx & 1) << 3);
            fsm[(row * 2 + (w & 1)) * 3 + 0] = s0;
            fsm[(row * 2 + (w & 1)) * 3 + 1] = s1;
            fsm[(row * 2 + (w & 1)) * 3 + 2] = s2;
        }
    }
    __syncthreads();
    if (t < QTILE) {
        float s0 = fsm[(t * 2) * 3 + 0], s1 = fsm[(t * 2) * 3 + 1], s2 = fsm[(t * 2) * 3 + 2];
        ins3(fsm[(t * 2 + 1) * 3 + 0], s0, s1, s2);
        ins3(fsm[(t * 2 + 1) * 3 + 1], s0, s1, s2);
        ins3(fsm[(t * 2 + 1) * 3 + 2], s0, s1, s2);
        float* dst = g_partial + (((size_t)qt * NS + slice) * QTILE + t) * 3;
        dst[0] = s0; dst[1] = s1; dst[2] = s2;
    }
}

// ---------------- 4) merge slices, per-query dist, per-batch top-8 mean ----------------
__global__ void finalize_kernel(float* __restrict__ out) {
    __shared__ float cand[64];
    const int b = blockIdx.x, t = threadIdx.x;     // 256 threads = 256 patches of batch b
    const int lane = t & 31, wid = t >> 5;
    const int q = b * 256 + t;
    const int qt = q >> 7, row = q & 127;
    float s0 = -3.f, s1 = -3.f, s2 = -3.f;
    for (int s = 0; s < NS; s++) {
        const float* p = g_partial + (((size_t)qt * NS + s) * QTILE + row) * 3;
        ins3(p[0], s0, s1, s2); ins3(p[1], s0, s1, s2); ins3(p[2], s0, s1, s2);
    }
    float d0 = sqrtf(fmaxf(2.f - 2.f * s0, 0.f));
    float d1 = sqrtf(fmaxf(2.f - 2.f * s1, 0.f));
    float d2 = sqrtf(fmaxf(2.f - 2.f * s2, 0.f));
    float x = (d0 + d1 + d2) * (1.f / 3.f);

    // stage 1: per-warp top-8 by knockout max-reduction -> 64 candidates
    for (int it = 0; it < 8; it++) {
        float mx = x;
        for (int m = 16; m > 0; m >>= 1)
            mx = fmaxf(mx, __shfl_xor_sync(0xffffffffu, mx, m));
        unsigned bal = __ballot_sync(0xffffffffu, x == mx);
        if (lane == 0) cand[wid * 8 + it] = mx;
        if (lane == (int)(__ffs(bal) - 1)) x = -1e30f;
    }
    __syncthreads();

    // stage 2: warp 0 knockout over the 64 candidates (2 regs/lane, parallel)
    if (wid == 0) {
        float v0 = cand[lane], v1 = cand[32 + lane];
        float sum = 0.f;
#pragma unroll
        for (int it = 0; it < 8; it++) {
            float lm = fmaxf(v0, v1);
            float mx = lm;
#pragma unroll
            for (int m = 16; m > 0; m >>= 1)
                mx = fmaxf(mx, __shfl_xor_sync(0xffffffffu, mx, m));
            sum += mx;
            unsigned bal = __ballot_sync(0xffffffffu, lm == mx);
            if (lane == (int)(__ffs(bal) - 1)) {
                if (v0 == mx) v0 = -1e30f; else v1 = -1e30f;
            }
        }
        if (lane == 0) out[b] = sum * 0.125f;   // k = ceil(256*0.03) = 8
    }
}

// ---------------- launch ----------------
extern "C" void kernel_launch(void* const* d_in, const int* in_sizes, int n_in,
                              void* d_out, int out_size) {
    const float* fm   = (const float*)d_in[0];  // [8,112,16,16]
    const float* w    = (const float*)d_in[1];  // [128,112]
    const float* bank = (const float*)d_in[2];  // [200000,128]
    float* out = (float*)d_out;                 // [8]

    const int embed_smem = (DD * WSTR + 8 * C_INN + 8 * DD + 8) * (int)sizeof(float);
    cudaFuncSetAttribute(embed_kernel,
                         cudaFuncAttributeMaxDynamicSharedMemorySize, embed_smem);
    embed_kernel<<<QTOT / 8, 128, embed_smem>>>(fm, w);
    bank_norm_kernel<<<NB_PAD / 128, 512>>>(bank);

    const int smem_bytes = 3 * TILE_SM * (int)sizeof(__nv_bfloat16);  // 104448
    cudaFuncSetAttribute(sim_topk_kernel,
                         cudaFuncAttributeMaxDynamicSharedMemorySize, smem_bytes);
    dim3 grid(NS, QT);
    sim_topk_kernel<<<grid, 256, smem_bytes>>>();

    finalize_kernel<<<BQ, 256>>>(out);
}